// round 13
// baseline (speedup 1.0000x reference)
#include <cuda_runtime.h>
#include <cuda_fp16.h>
#include <cstdint>

// Problem constants
#define S_LEN 2048
#define D_DIM 1024
#define NB    4
#define NH    16
#define DHD   64
#define M_ROWS (NB * S_LEN)   // 8192
#define NQKV  (3 * D_DIM)     // 3072

// Scratch (device globals: allocation-free per harness rules)
__device__ __half g_xh   [M_ROWS * D_DIM];
__device__ __half g_wqkvh[NQKV * D_DIM];
__device__ __half g_woh  [D_DIM * D_DIM];
__device__ __half g_QKVh [M_ROWS * NQKV];
__device__ __half g_aoh  [M_ROWS * D_DIM];

// ===========================================================================
// Helpers
// ===========================================================================
__device__ __forceinline__ uint32_t f2h2(float lo, float hi) {
    uint32_t u;
    asm("cvt.rn.f16x2.f32 %0, %1, %2;" : "=r"(u) : "f"(hi), "f"(lo));
    return u;
}

__device__ __forceinline__ void mma_f16(float c[4], const uint32_t a[4],
                                        const uint32_t b[2]) {
    asm volatile(
        "mma.sync.aligned.m16n8k16.row.col.f32.f16.f16.f32 "
        "{%0,%1,%2,%3}, {%4,%5,%6,%7}, {%8,%9}, {%0,%1,%2,%3};"
        : "+f"(c[0]), "+f"(c[1]), "+f"(c[2]), "+f"(c[3])
        : "r"(a[0]), "r"(a[1]), "r"(a[2]), "r"(a[3]), "r"(b[0]), "r"(b[1]));
}

__device__ __forceinline__ void ldm_x4(uint32_t& r0, uint32_t& r1,
                                       uint32_t& r2, uint32_t& r3,
                                       uint32_t addr) {
    asm volatile("ldmatrix.sync.aligned.m8n8.x4.shared.b16 {%0,%1,%2,%3}, [%4];"
                 : "=r"(r0), "=r"(r1), "=r"(r2), "=r"(r3) : "r"(addr));
}
__device__ __forceinline__ void ldm_x4_t(uint32_t& r0, uint32_t& r1,
                                         uint32_t& r2, uint32_t& r3,
                                         uint32_t addr) {
    asm volatile("ldmatrix.sync.aligned.m8n8.x4.trans.shared.b16 {%0,%1,%2,%3}, [%4];"
                 : "=r"(r0), "=r"(r1), "=r"(r2), "=r"(r3) : "r"(addr));
}

// ===========================================================================
// fp32 -> fp16 converts
// ===========================================================================
__global__ void __launch_bounds__(256) f2h_kernel(const float* __restrict__ src,
                                                  __half* __restrict__ dst,
                                                  int n4) {
    const int nt = gridDim.x * 256;
    const int i0 = blockIdx.x * 256 + threadIdx.x;
    float4 v0 = ((const float4*)src)[i0];
    float4 v1 = ((const float4*)src)[i0 + nt];
    float4 v2 = ((const float4*)src)[i0 + 2 * nt];
    float4 v3 = ((const float4*)src)[i0 + 3 * nt];
    ((uint2*)dst)[i0]          = make_uint2(f2h2(v0.x, v0.y), f2h2(v0.z, v0.w));
    ((uint2*)dst)[i0 + nt]     = make_uint2(f2h2(v1.x, v1.y), f2h2(v1.z, v1.w));
    ((uint2*)dst)[i0 + 2 * nt] = make_uint2(f2h2(v2.x, v2.y), f2h2(v2.z, v2.w));
    ((uint2*)dst)[i0 + 3 * nt] = make_uint2(f2h2(v3.x, v3.y), f2h2(v3.z, v3.w));
}

__global__ void __launch_bounds__(256) f2h_w_kernel(const float* __restrict__ wq,
                                                    const float* __restrict__ wk,
                                                    const float* __restrict__ wv,
                                                    const float* __restrict__ wo,
                                                    __half* __restrict__ wqkvh,
                                                    __half* __restrict__ woh,
                                                    int w4) {
    const int blocks_per_seg = gridDim.x / 4;
    const int seg = blockIdx.x / blocks_per_seg;
    const int ib  = blockIdx.x % blocks_per_seg;
    const float* src = (seg == 0) ? wq : (seg == 1) ? wk : (seg == 2) ? wv : wo;
    __half* dst = (seg < 3) ? (wqkvh + (size_t)seg * (size_t)w4 * 4) : woh;
    const int nt = blocks_per_seg * 256;
    const int i0 = ib * 256 + threadIdx.x;
#pragma unroll
    for (int p = 0; p < 4; p++) {
        const int i = i0 + p * nt;
        float4 v = ((const float4*)src)[i];
        ((uint2*)dst)[i] = make_uint2(f2h2(v.x, v.y), f2h2(v.z, v.w));
    }
}

// ===========================================================================
// fp16 NT GEMM (R10 config, unchanged): CTA 128x128, 128 threads
// (4 warps 2Mx2N, 64x64), KC=64, 3-stage cp.async, occupancy 2.
// ===========================================================================
#define GKC        64
#define GSTR       72
#define GSTAGES    3
#define GTILE_H    (128 * GSTR)
#define GSTAGE_H   (2 * GTILE_H)
#define GEMM_SMEM  (GSTAGES * GSTAGE_H * 2)   // 110592 bytes

template <typename OutT>
__global__ void __launch_bounds__(128, 2) gemm_h(const __half* __restrict__ A,
                                                 const __half* __restrict__ B,
                                                 OutT* __restrict__ C,
                                                 int M, int N, int K) {
    extern __shared__ __half sh[];
    const uint32_t sbase = (uint32_t)__cvta_generic_to_shared(sh);

    const int tid  = threadIdx.x;
    const int lane = tid & 31;
    const int wid  = tid >> 5;
    const int g    = lane >> 2;
    const int t    = lane & 3;
    const int wm   = (wid & 1) * 64;
    const int wn   = (wid >> 1) * 64;
    const int bm   = blockIdx.y * 128;
    const int bn   = blockIdx.x * 128;

    const int arow = (lane & 7) + ((lane & 8) ? 8 : 0);
    const int acol = (lane & 16) ? 8 : 0;
    const int brow = (lane & 7) + ((lane & 16) ? 8 : 0);
    const int bcol = (lane & 8) ? 8 : 0;

    float acc[4][8][4];
#pragma unroll
    for (int i = 0; i < 4; i++)
#pragma unroll
        for (int j = 0; j < 8; j++)
#pragma unroll
            for (int q = 0; q < 4; q++) acc[i][j][q] = 0.0f;

    const int CHUNKS = K / GKC;

    auto issue = [&](int chunk, int st) {
        const __half* Agc = A + (size_t)bm * K + chunk * GKC;
        const __half* Bgc = B + (size_t)bn * K + chunk * GKC;
        const uint32_t sA = sbase + (uint32_t)(st * GSTAGE_H) * 2;
        const uint32_t sB = sA + (uint32_t)GTILE_H * 2;
#pragma unroll
        for (int i = 0; i < 8; i++) {
            const int cid = tid + i * 128;
            const int row = cid >> 3, c16 = cid & 7;
            const __half* ga = Agc + (size_t)row * K + c16 * 8;
            const __half* gb = Bgc + (size_t)row * K + c16 * 8;
            const uint32_t da = sA + (uint32_t)(row * GSTR + c16 * 8) * 2;
            const uint32_t db = sB + (uint32_t)(row * GSTR + c16 * 8) * 2;
            asm volatile("cp.async.cg.shared.global [%0], [%1], 16;" :: "r"(da), "l"(ga));
            asm volatile("cp.async.cg.shared.global [%0], [%1], 16;" :: "r"(db), "l"(gb));
        }
    };

#pragma unroll
    for (int s = 0; s < GSTAGES - 1; s++) {
        issue(s, s);
        asm volatile("cp.async.commit_group;");
    }

    for (int c = 0; c < CHUNKS; c++) {
        const int nc = c + GSTAGES - 1;
        if (nc < CHUNKS) issue(nc, nc % GSTAGES);
        asm volatile("cp.async.commit_group;");
        asm volatile("cp.async.wait_group 2;");
        __syncthreads();

        const int st = c % GSTAGES;
        const uint32_t aBase = sbase + (uint32_t)(st * GSTAGE_H) * 2;
        const uint32_t bBase = aBase + (uint32_t)GTILE_H * 2;

#pragma unroll
        for (int kb = 0; kb < 4; kb++) {
            uint32_t af[4][4], bf[8][2];
#pragma unroll
            for (int im = 0; im < 4; im++) {
                const uint32_t addr =
                    aBase + (uint32_t)((wm + im * 16 + arow) * GSTR + kb * 16 + acol) * 2;
                ldm_x4(af[im][0], af[im][1], af[im][2], af[im][3], addr);
            }
#pragma unroll
            for (int p = 0; p < 4; p++) {
                uint32_t r0, r1, r2, r3;
                const uint32_t addr =
                    bBase + (uint32_t)((wn + p * 16 + brow) * GSTR + kb * 16 + bcol) * 2;
                ldm_x4(r0, r1, r2, r3, addr);
                bf[2 * p][0] = r0; bf[2 * p][1] = r1;
                bf[2 * p + 1][0] = r2; bf[2 * p + 1][1] = r3;
            }
#pragma unroll
            for (int im = 0; im < 4; im++)
#pragma unroll
                for (int jn = 0; jn < 8; jn++)
                    mma_f16(acc[im][jn], af[im], bf[jn]);
        }
        __syncthreads();
    }

#pragma unroll
    for (int im = 0; im < 4; im++) {
#pragma unroll
        for (int jn = 0; jn < 8; jn++) {
            const int row = bm + wm + im * 16 + g;
            const int col = bn + wn + jn * 8 + 2 * t;
            if constexpr (sizeof(OutT) == 2) {
                *(uint32_t*)((__half*)C + (size_t)row * N + col) =
                    f2h2(acc[im][jn][0], acc[im][jn][1]);
                *(uint32_t*)((__half*)C + (size_t)(row + 8) * N + col) =
                    f2h2(acc[im][jn][2], acc[im][jn][3]);
            } else {
                *(float2*)((float*)C + (size_t)row * N + col) =
                    make_float2(acc[im][jn][0], acc[im][jn][1]);
                *(float2*)((float*)C + (size_t)(row + 8) * N + col) =
                    make_float2(acc[im][jn][2], acc[im][jn][3]);
            }
        }
    }
}

// ===========================================================================
// Causal flash attention (R11 config restored): fp16 in/out, fp32 accum.
// 2-buffer KV ring (&1 addressing), barrier -> issue -> wait -> barrier,
// reversed q-tile launch order, fma+exp2 softmax.
// ===========================================================================
#define QT   128
#define KT   64
#define AST  72
#define ATTN_SMEM ((9216 + 18432) * 2)   // 55296 bytes
#define C_SEXP 0.180336880f              // 0.125 * log2(e)

__global__ void __launch_bounds__(256, 2) attn_mma(const __half* __restrict__ QKV,
                                                   __half* __restrict__ O) {
    extern __shared__ __half ash[];
    const uint32_t sbase = (uint32_t)__cvta_generic_to_shared(ash);
    const uint32_t qsm = sbase;

    const int bh = blockIdx.y;
    const int b  = bh >> 4;
    const int h  = bh & 15;
    // Reversed order: most expensive q-tiles first.
    const int q0 = (int)(gridDim.x - 1 - blockIdx.x) * QT;

    const int tid  = threadIdx.x;
    const int lane = tid & 31;
    const int wid  = tid >> 5;
    const int g    = lane >> 2;
    const int t    = lane & 3;
    const int row0 = wid * 16;

    const int arow = (lane & 7) + ((lane & 8) ? 8 : 0);
    const int acol = (lane & 16) ? 8 : 0;
    const int brow = (lane & 7) + ((lane & 16) ? 8 : 0);
    const int bcol = (lane & 8) ? 8 : 0;

    const size_t qkv_base = ((size_t)b * S_LEN) * NQKV + (size_t)h * DHD;
    const __half* Qg = QKV + qkv_base;
    const __half* Kg = QKV + qkv_base + D_DIM;
    const __half* Vg = QKV + qkv_base + 2 * D_DIM;
    const size_t obase = ((size_t)b * S_LEN) * D_DIM + (size_t)h * DHD;

    const int ntiles = q0 / KT + 2;

    auto issueKV = [&](int tile) {
        const int st = tile & 1;
        const uint32_t kB = sbase + (uint32_t)(9216 + st * 9216) * 2;
        const uint32_t vB = kB + (uint32_t)4608 * 2;
        const __half* Kt = Kg + (size_t)(tile * KT) * NQKV;
        const __half* Vt = Vg + (size_t)(tile * KT) * NQKV;
#pragma unroll
        for (int i = 0; i < 2; i++) {
            const int cid = tid + i * 256;
            const int row = cid >> 3, c16 = cid & 7;
            const __half* gk = Kt + (size_t)row * NQKV + c16 * 8;
            const __half* gv = Vt + (size_t)row * NQKV + c16 * 8;
            const uint32_t dk = kB + (uint32_t)(row * AST + c16 * 8) * 2;
            const uint32_t dv = vB + (uint32_t)(row * AST + c16 * 8) * 2;
            asm volatile("cp.async.cg.shared.global [%0], [%1], 16;" :: "r"(dk), "l"(gk));
            asm volatile("cp.async.cg.shared.global [%0], [%1], 16;" :: "r"(dv), "l"(gv));
        }
        asm volatile("cp.async.commit_group;");
    };

    issueKV(0);

#pragma unroll
    for (int i = 0; i < 4; i++) {
        const int cid = tid + i * 256;
        const int row = cid >> 3, c16 = cid & 7;
        uint4 v = *(const uint4*)(Qg + (size_t)(q0 + row) * NQKV + c16 * 8);
        *(uint4*)(ash + row * AST + c16 * 8) = v;
    }
    __syncthreads();

    uint32_t qf[4][4];
#pragma unroll
    for (int kb = 0; kb < 4; kb++) {
        const uint32_t addr =
            qsm + (uint32_t)((row0 + arow) * AST + kb * 16 + acol) * 2;
        ldm_x4(qf[kb][0], qf[kb][1], qf[kb][2], qf[kb][3], addr);
    }

    // m/l tracked in UNSCALED logit domain; exp arg = (s - m) * C_SEXP via fma.
    float m0 = -1e30f, m1 = -1e30f, l0 = 0.0f, l1 = 0.0f;
    float o[8][4];
#pragma unroll
    for (int n = 0; n < 8; n++)
#pragma unroll
        for (int q = 0; q < 4; q++) o[n][q] = 0.0f;

    const int qg0 = q0 + row0 + g;
    const int qg1 = qg0 + 8;

    for (int tile = 0; tile < ntiles; tile++) {
        const int kv0 = tile * KT;

        __syncthreads();
        if (tile + 1 < ntiles) issueKV(tile + 1);
        else asm volatile("cp.async.commit_group;");
        asm volatile("cp.async.wait_group 1;");
        __syncthreads();

        const int st = tile & 1;
        const uint32_t kbase = sbase + (uint32_t)(9216 + st * 9216) * 2;
        const uint32_t vbase = kbase + (uint32_t)4608 * 2;

        if (kv0 <= q0 + row0 + 15) {
            float s[8][4];
#pragma unroll
            for (int n = 0; n < 8; n++)
#pragma unroll
                for (int q = 0; q < 4; q++) s[n][q] = 0.0f;

#pragma unroll
            for (int kb = 0; kb < 4; kb++) {
#pragma unroll
                for (int p = 0; p < 4; p++) {
                    uint32_t r0, r1, r2, r3;
                    const uint32_t addr =
                        kbase + (uint32_t)((p * 16 + brow) * AST + kb * 16 + bcol) * 2;
                    ldm_x4(r0, r1, r2, r3, addr);
                    uint32_t bf0[2] = {r0, r1};
                    uint32_t bf1[2] = {r2, r3};
                    mma_f16(s[2 * p],     qf[kb], bf0);
                    mma_f16(s[2 * p + 1], qf[kb], bf1);
                }
            }

            // ---- Causal mask (unscaled domain) ----
            if ((kv0 + KT - 1) > (q0 + row0)) {
#pragma unroll
                for (int n = 0; n < 8; n++) {
#pragma unroll
                    for (int e = 0; e < 2; e++) {
                        const int kg = kv0 + n * 8 + 2 * t + e;
                        if (kg > qg0) s[n][e]     = -1e30f;
                        if (kg > qg1) s[n][2 + e] = -1e30f;
                    }
                }
            }

            // ---- Online softmax: p = exp2(fma(s, C, -mn*C)) ----
            float mt0 = -1e30f, mt1 = -1e30f;
#pragma unroll
            for (int n = 0; n < 8; n++) {
                mt0 = fmaxf(mt0, fmaxf(s[n][0], s[n][1]));
                mt1 = fmaxf(mt1, fmaxf(s[n][2], s[n][3]));
            }
            mt0 = fmaxf(mt0, __shfl_xor_sync(0xffffffffu, mt0, 1));
            mt0 = fmaxf(mt0, __shfl_xor_sync(0xffffffffu, mt0, 2));
            mt1 = fmaxf(mt1, __shfl_xor_sync(0xffffffffu, mt1, 1));
            mt1 = fmaxf(mt1, __shfl_xor_sync(0xffffffffu, mt1, 2));

            const float mn0 = fmaxf(m0, mt0);
            const float mn1 = fmaxf(m1, mt1);
            const float cr0 = exp2f((m0 - mn0) * C_SEXP);
            const float cr1 = exp2f((m1 - mn1) * C_SEXP);
            m0 = mn0; m1 = mn1;
            const float d0 = -mn0 * C_SEXP;
            const float d1 = -mn1 * C_SEXP;

            float lt0 = 0.0f, lt1 = 0.0f;
#pragma unroll
            for (int n = 0; n < 8; n++) {
                s[n][0] = exp2f(fmaf(s[n][0], C_SEXP, d0));
                s[n][1] = exp2f(fmaf(s[n][1], C_SEXP, d0));
                s[n][2] = exp2f(fmaf(s[n][2], C_SEXP, d1));
                s[n][3] = exp2f(fmaf(s[n][3], C_SEXP, d1));
                lt0 += s[n][0] + s[n][1];
                lt1 += s[n][2] + s[n][3];
            }
            lt0 += __shfl_xor_sync(0xffffffffu, lt0, 1);
            lt0 += __shfl_xor_sync(0xffffffffu, lt0, 2);
            lt1 += __shfl_xor_sync(0xffffffffu, lt1, 1);
            lt1 += __shfl_xor_sync(0xffffffffu, lt1, 2);
            l0 = l0 * cr0 + lt0;
            l1 = l1 * cr1 + lt1;

#pragma unroll
            for (int n = 0; n < 8; n++) {
                o[n][0] *= cr0; o[n][1] *= cr0;
                o[n][2] *= cr1; o[n][3] *= cr1;
            }

#pragma unroll
            for (int kb = 0; kb < 4; kb++) {
                uint32_t ap[4];
                ap[0] = f2h2(s[2 * kb][0],     s[2 * kb][1]);
                ap[1] = f2h2(s[2 * kb][2],     s[2 * kb][3]);
                ap[2] = f2h2(s[2 * kb + 1][0], s[2 * kb + 1][1]);
                ap[3] = f2h2(s[2 * kb + 1][2], s[2 * kb + 1][3]);
#pragma unroll
                for (int p = 0; p < 4; p++) {
                    uint32_t r0, r1, r2, r3;
                    const uint32_t addr =
                        vbase + (uint32_t)((kb * 16 + arow) * AST + p * 16 + acol) * 2;
                    ldm_x4_t(r0, r1, r2, r3, addr);
                    uint32_t bf0[2] = {r0, r1};
                    uint32_t bf1[2] = {r2, r3};
                    mma_f16(o[2 * p],     ap, bf0);
                    mma_f16(o[2 * p + 1], ap, bf1);
                }
            }
        }
    }

    const float inv0 = 1.0f / l0;
    const float inv1 = 1.0f / l1;
#pragma unroll
    for (int n = 0; n < 8; n++) {
        const int col = n * 8 + 2 * t;
        *(uint32_t*)(O + obase + (size_t)qg0 * D_DIM + col) =
            f2h2(o[n][0] * inv0, o[n][1] * inv0);
        *(uint32_t*)(O + obase + (size_t)qg1 * D_DIM + col) =
            f2h2(o[n][2] * inv1, o[n][3] * inv1);
    }
}

// ===========================================================================
extern "C" void kernel_launch(void* const* d_in, const int* in_sizes, int n_in,
                              void* d_out, int out_size) {
    const float* x  = (const float*)d_in[0];
    const float* wq = (const float*)d_in[1];
    const float* wk = (const float*)d_in[2];
    const float* wv = (const float*)d_in[3];
    const float* wo = (const float*)d_in[4];
    float* out = (float*)d_out;

    __half *xh, *wqkvh, *woh, *QKVh, *aoh;
    cudaGetSymbolAddress((void**)&xh,    g_xh);
    cudaGetSymbolAddress((void**)&wqkvh, g_wqkvh);
    cudaGetSymbolAddress((void**)&woh,   g_woh);
    cudaGetSymbolAddress((void**)&QKVh,  g_QKVh);
    cudaGetSymbolAddress((void**)&aoh,   g_aoh);

    cudaFuncSetAttribute(gemm_h<__half>,
                         cudaFuncAttributeMaxDynamicSharedMemorySize, GEMM_SMEM);
    cudaFuncSetAttribute(gemm_h<float>,
                         cudaFuncAttributeMaxDynamicSharedMemorySize, GEMM_SMEM);
    cudaFuncSetAttribute(attn_mma,
                         cudaFuncAttributeMaxDynamicSharedMemorySize, ATTN_SMEM);

    const int X4 = M_ROWS * D_DIM / 4;   // 2097152
    const int W4 = D_DIM * D_DIM / 4;    // 262144
    f2h_kernel<<<X4 / 1024, 256>>>(x, xh, X4);
    f2h_w_kernel<<<4 * (W4 / 1024), 256>>>(wq, wk, wv, wo, wqkvh, woh, W4);

    gemm_h<__half><<<dim3(NQKV / 128, M_ROWS / 128), 128, GEMM_SMEM>>>(
        xh, wqkvh, QKVh, M_ROWS, NQKV, D_DIM);

    attn_mma<<<dim3(S_LEN / QT, NB * NH), 256, ATTN_SMEM>>>(QKVh, aoh);

    gemm_h<float><<<dim3(D_DIM / 128, M_ROWS / 128), 128, GEMM_SMEM>>>(
        aoh, woh, out, M_ROWS, D_DIM, D_DIM);
}

// round 14
// speedup vs baseline: 1.0114x; 1.0114x over previous
#include <cuda_runtime.h>
#include <cuda_fp16.h>
#include <cstdint>

// Problem constants
#define S_LEN 2048
#define D_DIM 1024
#define NB    4
#define NH    16
#define DHD   64
#define M_ROWS (NB * S_LEN)   // 8192
#define NQKV  (3 * D_DIM)     // 3072

// Scratch (device globals: allocation-free per harness rules)
__device__ __half g_xh   [M_ROWS * D_DIM];
__device__ __half g_wqkvh[NQKV * D_DIM];
__device__ __half g_woh  [D_DIM * D_DIM];
__device__ __half g_QKVh [M_ROWS * NQKV];
__device__ __half g_aoh  [M_ROWS * D_DIM];

// ===========================================================================
// Helpers
// ===========================================================================
__device__ __forceinline__ uint32_t f2h2(float lo, float hi) {
    uint32_t u;
    asm("cvt.rn.f16x2.f32 %0, %1, %2;" : "=r"(u) : "f"(hi), "f"(lo));
    return u;
}

__device__ __forceinline__ void mma_f16(float c[4], const uint32_t a[4],
                                        const uint32_t b[2]) {
    asm volatile(
        "mma.sync.aligned.m16n8k16.row.col.f32.f16.f16.f32 "
        "{%0,%1,%2,%3}, {%4,%5,%6,%7}, {%8,%9}, {%0,%1,%2,%3};"
        : "+f"(c[0]), "+f"(c[1]), "+f"(c[2]), "+f"(c[3])
        : "r"(a[0]), "r"(a[1]), "r"(a[2]), "r"(a[3]), "r"(b[0]), "r"(b[1]));
}

__device__ __forceinline__ void ldm_x4(uint32_t& r0, uint32_t& r1,
                                       uint32_t& r2, uint32_t& r3,
                                       uint32_t addr) {
    asm volatile("ldmatrix.sync.aligned.m8n8.x4.shared.b16 {%0,%1,%2,%3}, [%4];"
                 : "=r"(r0), "=r"(r1), "=r"(r2), "=r"(r3) : "r"(addr));
}
__device__ __forceinline__ void ldm_x4_t(uint32_t& r0, uint32_t& r1,
                                         uint32_t& r2, uint32_t& r3,
                                         uint32_t addr) {
    asm volatile("ldmatrix.sync.aligned.m8n8.x4.trans.shared.b16 {%0,%1,%2,%3}, [%4];"
                 : "=r"(r0), "=r"(r1), "=r"(r2), "=r"(r3) : "r"(addr));
}

// ===========================================================================
// fp32 -> fp16 converts: ONE launch for x + all four weight matrices.
// Blocks [0, 2048): x (2048*256*4 float4 = 8192*1024/4).
// Blocks [2048, 3072): four 256-block segments for wq/wk/wv/wo.
// ===========================================================================
#define XBLOCKS 2048
#define WBLOCKS_PER_SEG 256

__global__ void __launch_bounds__(256) f2h_all(const float* __restrict__ x,
                                               const float* __restrict__ wq,
                                               const float* __restrict__ wk,
                                               const float* __restrict__ wv,
                                               const float* __restrict__ wo,
                                               __half* __restrict__ xh,
                                               __half* __restrict__ wqkvh,
                                               __half* __restrict__ woh) {
    const int blk = blockIdx.x;
    if (blk < XBLOCKS) {
        const int nt = XBLOCKS * 256;
        const int i0 = blk * 256 + threadIdx.x;
#pragma unroll
        for (int p = 0; p < 4; p++) {
            const int i = i0 + p * nt;
            float4 v = ((const float4*)x)[i];
            ((uint2*)xh)[i] = make_uint2(f2h2(v.x, v.y), f2h2(v.z, v.w));
        }
    } else {
        const int wb  = blk - XBLOCKS;
        const int seg = wb / WBLOCKS_PER_SEG;
        const int ib  = wb % WBLOCKS_PER_SEG;
        const float* src = (seg == 0) ? wq : (seg == 1) ? wk : (seg == 2) ? wv : wo;
        __half* dst = (seg < 3) ? (wqkvh + (size_t)seg * D_DIM * D_DIM) : woh;
        const int nt = WBLOCKS_PER_SEG * 256;
        const int i0 = ib * 256 + threadIdx.x;
#pragma unroll
        for (int p = 0; p < 4; p++) {
            const int i = i0 + p * nt;
            float4 v = ((const float4*)src)[i];
            ((uint2*)dst)[i] = make_uint2(f2h2(v.x, v.y), f2h2(v.z, v.w));
        }
    }
}

// ===========================================================================
// fp16 NT GEMM: CTA 128x128, 128 threads (4 warps 2Mx2N, 64x64), KC=64,
// 3-stage cp.async, occupancy 2.
// R14: explicit fragment double-buffering — kb+1's ldmatrix issue BEFORE
// kb's mma (volatile asm preserves order, so without this the first mma of
// every kb-step serializes behind 29-cycle LDSM latency at 2 warps/SMSP).
// ===========================================================================
#define GKC        64
#define GSTR       72
#define GSTAGES    3
#define GTILE_H    (128 * GSTR)
#define GSTAGE_H   (2 * GTILE_H)
#define GEMM_SMEM  (GSTAGES * GSTAGE_H * 2)   // 110592 bytes

template <typename OutT>
__global__ void __launch_bounds__(128, 2) gemm_h(const __half* __restrict__ A,
                                                 const __half* __restrict__ B,
                                                 OutT* __restrict__ C,
                                                 int M, int N, int K) {
    extern __shared__ __half sh[];
    const uint32_t sbase = (uint32_t)__cvta_generic_to_shared(sh);

    const int tid  = threadIdx.x;
    const int lane = tid & 31;
    const int wid  = tid >> 5;
    const int g    = lane >> 2;
    const int t    = lane & 3;
    const int wm   = (wid & 1) * 64;
    const int wn   = (wid >> 1) * 64;
    const int bm   = blockIdx.y * 128;
    const int bn   = blockIdx.x * 128;

    const int arow = (lane & 7) + ((lane & 8) ? 8 : 0);
    const int acol = (lane & 16) ? 8 : 0;
    const int brow = (lane & 7) + ((lane & 16) ? 8 : 0);
    const int bcol = (lane & 8) ? 8 : 0;

    float acc[4][8][4];
#pragma unroll
    for (int i = 0; i < 4; i++)
#pragma unroll
        for (int j = 0; j < 8; j++)
#pragma unroll
            for (int q = 0; q < 4; q++) acc[i][j][q] = 0.0f;

    const int CHUNKS = K / GKC;

    auto issue = [&](int chunk, int st) {
        const __half* Agc = A + (size_t)bm * K + chunk * GKC;
        const __half* Bgc = B + (size_t)bn * K + chunk * GKC;
        const uint32_t sA = sbase + (uint32_t)(st * GSTAGE_H) * 2;
        const uint32_t sB = sA + (uint32_t)GTILE_H * 2;
#pragma unroll
        for (int i = 0; i < 8; i++) {
            const int cid = tid + i * 128;
            const int row = cid >> 3, c16 = cid & 7;
            const __half* ga = Agc + (size_t)row * K + c16 * 8;
            const __half* gb = Bgc + (size_t)row * K + c16 * 8;
            const uint32_t da = sA + (uint32_t)(row * GSTR + c16 * 8) * 2;
            const uint32_t db = sB + (uint32_t)(row * GSTR + c16 * 8) * 2;
            asm volatile("cp.async.cg.shared.global [%0], [%1], 16;" :: "r"(da), "l"(ga));
            asm volatile("cp.async.cg.shared.global [%0], [%1], 16;" :: "r"(db), "l"(gb));
        }
    };

#pragma unroll
    for (int s = 0; s < GSTAGES - 1; s++) {
        issue(s, s);
        asm volatile("cp.async.commit_group;");
    }

    // Fragment double buffers
    uint32_t af[2][4][4], bf[2][8][2];

    for (int c = 0; c < CHUNKS; c++) {
        const int nc = c + GSTAGES - 1;
        if (nc < CHUNKS) issue(nc, nc % GSTAGES);
        asm volatile("cp.async.commit_group;");
        asm volatile("cp.async.wait_group 2;");
        __syncthreads();

        const int st = c % GSTAGES;
        const uint32_t aBase = sbase + (uint32_t)(st * GSTAGE_H) * 2;
        const uint32_t bBase = aBase + (uint32_t)GTILE_H * 2;

        // Load kb=0 fragments into buffer 0
#pragma unroll
        for (int im = 0; im < 4; im++) {
            const uint32_t addr =
                aBase + (uint32_t)((wm + im * 16 + arow) * GSTR + acol) * 2;
            ldm_x4(af[0][im][0], af[0][im][1], af[0][im][2], af[0][im][3], addr);
        }
#pragma unroll
        for (int p = 0; p < 4; p++) {
            uint32_t r0, r1, r2, r3;
            const uint32_t addr =
                bBase + (uint32_t)((wn + p * 16 + brow) * GSTR + bcol) * 2;
            ldm_x4(r0, r1, r2, r3, addr);
            bf[0][2 * p][0] = r0; bf[0][2 * p][1] = r1;
            bf[0][2 * p + 1][0] = r2; bf[0][2 * p + 1][1] = r3;
        }

#pragma unroll
        for (int kb = 0; kb < 4; kb++) {
            const int cur = kb & 1;
            // Prefetch kb+1 fragments into the other buffer BEFORE kb's mmas
            if (kb < 3) {
                const int nxt = (kb + 1) & 1;
#pragma unroll
                for (int im = 0; im < 4; im++) {
                    const uint32_t addr = aBase +
                        (uint32_t)((wm + im * 16 + arow) * GSTR + (kb + 1) * 16 + acol) * 2;
                    ldm_x4(af[nxt][im][0], af[nxt][im][1],
                           af[nxt][im][2], af[nxt][im][3], addr);
                }
#pragma unroll
                for (int p = 0; p < 4; p++) {
                    uint32_t r0, r1, r2, r3;
                    const uint32_t addr = bBase +
                        (uint32_t)((wn + p * 16 + brow) * GSTR + (kb + 1) * 16 + bcol) * 2;
                    ldm_x4(r0, r1, r2, r3, addr);
                    bf[nxt][2 * p][0] = r0; bf[nxt][2 * p][1] = r1;
                    bf[nxt][2 * p + 1][0] = r2; bf[nxt][2 * p + 1][1] = r3;
                }
            }
#pragma unroll
            for (int im = 0; im < 4; im++)
#pragma unroll
                for (int jn = 0; jn < 8; jn++)
                    mma_f16(acc[im][jn], af[cur][im], bf[cur][jn]);
        }
        __syncthreads();
    }

#pragma unroll
    for (int im = 0; im < 4; im++) {
#pragma unroll
        for (int jn = 0; jn < 8; jn++) {
            const int row = bm + wm + im * 16 + g;
            const int col = bn + wn + jn * 8 + 2 * t;
            if constexpr (sizeof(OutT) == 2) {
                *(uint32_t*)((__half*)C + (size_t)row * N + col) =
                    f2h2(acc[im][jn][0], acc[im][jn][1]);
                *(uint32_t*)((__half*)C + (size_t)(row + 8) * N + col) =
                    f2h2(acc[im][jn][2], acc[im][jn][3]);
            } else {
                *(float2*)((float*)C + (size_t)row * N + col) =
                    make_float2(acc[im][jn][0], acc[im][jn][1]);
                *(float2*)((float*)C + (size_t)(row + 8) * N + col) =
                    make_float2(acc[im][jn][2], acc[im][jn][3]);
            }
        }
    }
}

// ===========================================================================
// Causal flash attention (unchanged from best config): fp16 in/out, fp32
// accum; 2-buffer KV ring, reversed q-tile order, fma+exp2 softmax.
// ===========================================================================
#define QT   128
#define KT   64
#define AST  72
#define ATTN_SMEM ((9216 + 18432) * 2)   // 55296 bytes
#define C_SEXP 0.180336880f              // 0.125 * log2(e)

__global__ void __launch_bounds__(256, 2) attn_mma(const __half* __restrict__ QKV,
                                                   __half* __restrict__ O) {
    extern __shared__ __half ash[];
    const uint32_t sbase = (uint32_t)__cvta_generic_to_shared(ash);
    const uint32_t qsm = sbase;

    const int bh = blockIdx.y;
    const int b  = bh >> 4;
    const int h  = bh & 15;
    const int q0 = (int)(gridDim.x - 1 - blockIdx.x) * QT;

    const int tid  = threadIdx.x;
    const int lane = tid & 31;
    const int wid  = tid >> 5;
    const int g    = lane >> 2;
    const int t    = lane & 3;
    const int row0 = wid * 16;

    const int arow = (lane & 7) + ((lane & 8) ? 8 : 0);
    const int acol = (lane & 16) ? 8 : 0;
    const int brow = (lane & 7) + ((lane & 16) ? 8 : 0);
    const int bcol = (lane & 8) ? 8 : 0;

    const size_t qkv_base = ((size_t)b * S_LEN) * NQKV + (size_t)h * DHD;
    const __half* Qg = QKV + qkv_base;
    const __half* Kg = QKV + qkv_base + D_DIM;
    const __half* Vg = QKV + qkv_base + 2 * D_DIM;
    const size_t obase = ((size_t)b * S_LEN) * D_DIM + (size_t)h * DHD;

    const int ntiles = q0 / KT + 2;

    auto issueKV = [&](int tile) {
        const int st = tile & 1;
        const uint32_t kB = sbase + (uint32_t)(9216 + st * 9216) * 2;
        const uint32_t vB = kB + (uint32_t)4608 * 2;
        const __half* Kt = Kg + (size_t)(tile * KT) * NQKV;
        const __half* Vt = Vg + (size_t)(tile * KT) * NQKV;
#pragma unroll
        for (int i = 0; i < 2; i++) {
            const int cid = tid + i * 256;
            const int row = cid >> 3, c16 = cid & 7;
            const __half* gk = Kt + (size_t)row * NQKV + c16 * 8;
            const __half* gv = Vt + (size_t)row * NQKV + c16 * 8;
            const uint32_t dk = kB + (uint32_t)(row * AST + c16 * 8) * 2;
            const uint32_t dv = vB + (uint32_t)(row * AST + c16 * 8) * 2;
            asm volatile("cp.async.cg.shared.global [%0], [%1], 16;" :: "r"(dk), "l"(gk));
            asm volatile("cp.async.cg.shared.global [%0], [%1], 16;" :: "r"(dv), "l"(gv));
        }
        asm volatile("cp.async.commit_group;");
    };

    issueKV(0);

#pragma unroll
    for (int i = 0; i < 4; i++) {
        const int cid = tid + i * 256;
        const int row = cid >> 3, c16 = cid & 7;
        uint4 v = *(const uint4*)(Qg + (size_t)(q0 + row) * NQKV + c16 * 8);
        *(uint4*)(ash + row * AST + c16 * 8) = v;
    }
    __syncthreads();

    uint32_t qf[4][4];
#pragma unroll
    for (int kb = 0; kb < 4; kb++) {
        const uint32_t addr =
            qsm + (uint32_t)((row0 + arow) * AST + kb * 16 + acol) * 2;
        ldm_x4(qf[kb][0], qf[kb][1], qf[kb][2], qf[kb][3], addr);
    }

    float m0 = -1e30f, m1 = -1e30f, l0 = 0.0f, l1 = 0.0f;
    float o[8][4];
#pragma unroll
    for (int n = 0; n < 8; n++)
#pragma unroll
        for (int q = 0; q < 4; q++) o[n][q] = 0.0f;

    const int qg0 = q0 + row0 + g;
    const int qg1 = qg0 + 8;

    for (int tile = 0; tile < ntiles; tile++) {
        const int kv0 = tile * KT;

        __syncthreads();
        if (tile + 1 < ntiles) issueKV(tile + 1);
        else asm volatile("cp.async.commit_group;");
        asm volatile("cp.async.wait_group 1;");
        __syncthreads();

        const int st = tile & 1;
        const uint32_t kbase = sbase + (uint32_t)(9216 + st * 9216) * 2;
        const uint32_t vbase = kbase + (uint32_t)4608 * 2;

        if (kv0 <= q0 + row0 + 15) {
            float s[8][4];
#pragma unroll
            for (int n = 0; n < 8; n++)
#pragma unroll
                for (int q = 0; q < 4; q++) s[n][q] = 0.0f;

#pragma unroll
            for (int kb = 0; kb < 4; kb++) {
#pragma unroll
                for (int p = 0; p < 4; p++) {
                    uint32_t r0, r1, r2, r3;
                    const uint32_t addr =
                        kbase + (uint32_t)((p * 16 + brow) * AST + kb * 16 + bcol) * 2;
                    ldm_x4(r0, r1, r2, r3, addr);
                    uint32_t bf0[2] = {r0, r1};
                    uint32_t bf1[2] = {r2, r3};
                    mma_f16(s[2 * p],     qf[kb], bf0);
                    mma_f16(s[2 * p + 1], qf[kb], bf1);
                }
            }

            if ((kv0 + KT - 1) > (q0 + row0)) {
#pragma unroll
                for (int n = 0; n < 8; n++) {
#pragma unroll
                    for (int e = 0; e < 2; e++) {
                        const int kg = kv0 + n * 8 + 2 * t + e;
                        if (kg > qg0) s[n][e]     = -1e30f;
                        if (kg > qg1) s[n][2 + e] = -1e30f;
                    }
                }
            }

            float mt0 = -1e30f, mt1 = -1e30f;
#pragma unroll
            for (int n = 0; n < 8; n++) {
                mt0 = fmaxf(mt0, fmaxf(s[n][0], s[n][1]));
                mt1 = fmaxf(mt1, fmaxf(s[n][2], s[n][3]));
            }
            mt0 = fmaxf(mt0, __shfl_xor_sync(0xffffffffu, mt0, 1));
            mt0 = fmaxf(mt0, __shfl_xor_sync(0xffffffffu, mt0, 2));
            mt1 = fmaxf(mt1, __shfl_xor_sync(0xffffffffu, mt1, 1));
            mt1 = fmaxf(mt1, __shfl_xor_sync(0xffffffffu, mt1, 2));

            const float mn0 = fmaxf(m0, mt0);
            const float mn1 = fmaxf(m1, mt1);
            const float cr0 = exp2f((m0 - mn0) * C_SEXP);
            const float cr1 = exp2f((m1 - mn1) * C_SEXP);
            m0 = mn0; m1 = mn1;
            const float d0 = -mn0 * C_SEXP;
            const float d1 = -mn1 * C_SEXP;

            float lt0 = 0.0f, lt1 = 0.0f;
#pragma unroll
            for (int n = 0; n < 8; n++) {
                s[n][0] = exp2f(fmaf(s[n][0], C_SEXP, d0));
                s[n][1] = exp2f(fmaf(s[n][1], C_SEXP, d0));
                s[n][2] = exp2f(fmaf(s[n][2], C_SEXP, d1));
                s[n][3] = exp2f(fmaf(s[n][3], C_SEXP, d1));
                lt0 += s[n][0] + s[n][1];
                lt1 += s[n][2] + s[n][3];
            }
            lt0 += __shfl_xor_sync(0xffffffffu, lt0, 1);
            lt0 += __shfl_xor_sync(0xffffffffu, lt0, 2);
            lt1 += __shfl_xor_sync(0xffffffffu, lt1, 1);
            lt1 += __shfl_xor_sync(0xffffffffu, lt1, 2);
            l0 = l0 * cr0 + lt0;
            l1 = l1 * cr1 + lt1;

#pragma unroll
            for (int n = 0; n < 8; n++) {
                o[n][0] *= cr0; o[n][1] *= cr0;
                o[n][2] *= cr1; o[n][3] *= cr1;
            }

#pragma unroll
            for (int kb = 0; kb < 4; kb++) {
                uint32_t ap[4];
                ap[0] = f2h2(s[2 * kb][0],     s[2 * kb][1]);
                ap[1] = f2h2(s[2 * kb][2],     s[2 * kb][3]);
                ap[2] = f2h2(s[2 * kb + 1][0], s[2 * kb + 1][1]);
                ap[3] = f2h2(s[2 * kb + 1][2], s[2 * kb + 1][3]);
#pragma unroll
                for (int p = 0; p < 4; p++) {
                    uint32_t r0, r1, r2, r3;
                    const uint32_t addr =
                        vbase + (uint32_t)((kb * 16 + arow) * AST + p * 16 + acol) * 2;
                    ldm_x4_t(r0, r1, r2, r3, addr);
                    uint32_t bf0[2] = {r0, r1};
                    uint32_t bf1[2] = {r2, r3};
                    mma_f16(o[2 * p],     ap, bf0);
                    mma_f16(o[2 * p + 1], ap, bf1);
                }
            }
        }
    }

    const float inv0 = 1.0f / l0;
    const float inv1 = 1.0f / l1;
#pragma unroll
    for (int n = 0; n < 8; n++) {
        const int col = n * 8 + 2 * t;
        *(uint32_t*)(O + obase + (size_t)qg0 * D_DIM + col) =
            f2h2(o[n][0] * inv0, o[n][1] * inv0);
        *(uint32_t*)(O + obase + (size_t)qg1 * D_DIM + col) =
            f2h2(o[n][2] * inv1, o[n][3] * inv1);
    }
}

// ===========================================================================
extern "C" void kernel_launch(void* const* d_in, const int* in_sizes, int n_in,
                              void* d_out, int out_size) {
    const float* x  = (const float*)d_in[0];
    const float* wq = (const float*)d_in[1];
    const float* wk = (const float*)d_in[2];
    const float* wv = (const float*)d_in[3];
    const float* wo = (const float*)d_in[4];
    float* out = (float*)d_out;

    __half *xh, *wqkvh, *woh, *QKVh, *aoh;
    cudaGetSymbolAddress((void**)&xh,    g_xh);
    cudaGetSymbolAddress((void**)&wqkvh, g_wqkvh);
    cudaGetSymbolAddress((void**)&woh,   g_woh);
    cudaGetSymbolAddress((void**)&QKVh,  g_QKVh);
    cudaGetSymbolAddress((void**)&aoh,   g_aoh);

    cudaFuncSetAttribute(gemm_h<__half>,
                         cudaFuncAttributeMaxDynamicSharedMemorySize, GEMM_SMEM);
    cudaFuncSetAttribute(gemm_h<float>,
                         cudaFuncAttributeMaxDynamicSharedMemorySize, GEMM_SMEM);
    cudaFuncSetAttribute(attn_mma,
                         cudaFuncAttributeMaxDynamicSharedMemorySize, ATTN_SMEM);

    // One convert launch: x + wq/wk/wv/wo
    f2h_all<<<XBLOCKS + 4 * WBLOCKS_PER_SEG, 256>>>(x, wq, wk, wv, wo,
                                                    xh, wqkvh, woh);

    gemm_h<__half><<<dim3(NQKV / 128, M_ROWS / 128), 128, GEMM_SMEM>>>(
        xh, wqkvh, QKVh, M_ROWS, NQKV, D_DIM);

    attn_mma<<<dim3(S_LEN / QT, NB * NH), 256, ATTN_SMEM>>>(QKVh, aoh);

    gemm_h<float><<<dim3(D_DIM / 128, M_ROWS / 128), 128, GEMM_SMEM>>>(
        aoh, woh, out, M_ROWS, D_DIM, D_DIM);
}

// round 15
// speedup vs baseline: 1.0288x; 1.0172x over previous
#include <cuda_runtime.h>
#include <cuda_fp16.h>
#include <cstdint>

// Problem constants
#define S_LEN 2048
#define D_DIM 1024
#define NB    4
#define NH    16
#define DHD   64
#define M_ROWS (NB * S_LEN)   // 8192
#define NQKV  (3 * D_DIM)     // 3072

// Scratch (device globals: allocation-free per harness rules)
__device__ __half g_xh   [M_ROWS * D_DIM];
__device__ __half g_wqkvh[NQKV * D_DIM];
__device__ __half g_woh  [D_DIM * D_DIM];
__device__ __half g_QKVh [M_ROWS * NQKV];
__device__ __half g_aoh  [M_ROWS * D_DIM];

// ===========================================================================
// Helpers
// ===========================================================================
__device__ __forceinline__ uint32_t f2h2(float lo, float hi) {
    uint32_t u;
    asm("cvt.rn.f16x2.f32 %0, %1, %2;" : "=r"(u) : "f"(hi), "f"(lo));
    return u;
}

__device__ __forceinline__ uint32_t ex2_h2(uint32_t arg) {
    uint32_t r;
    asm("ex2.approx.f16x2 %0, %1;" : "=r"(r) : "r"(arg));
    return r;
}

__device__ __forceinline__ void mma_f16(float c[4], const uint32_t a[4],
                                        const uint32_t b[2]) {
    asm volatile(
        "mma.sync.aligned.m16n8k16.row.col.f32.f16.f16.f32 "
        "{%0,%1,%2,%3}, {%4,%5,%6,%7}, {%8,%9}, {%0,%1,%2,%3};"
        : "+f"(c[0]), "+f"(c[1]), "+f"(c[2]), "+f"(c[3])
        : "r"(a[0]), "r"(a[1]), "r"(a[2]), "r"(a[3]), "r"(b[0]), "r"(b[1]));
}

__device__ __forceinline__ void ldm_x4(uint32_t& r0, uint32_t& r1,
                                       uint32_t& r2, uint32_t& r3,
                                       uint32_t addr) {
    asm volatile("ldmatrix.sync.aligned.m8n8.x4.shared.b16 {%0,%1,%2,%3}, [%4];"
                 : "=r"(r0), "=r"(r1), "=r"(r2), "=r"(r3) : "r"(addr));
}
__device__ __forceinline__ void ldm_x4_t(uint32_t& r0, uint32_t& r1,
                                         uint32_t& r2, uint32_t& r3,
                                         uint32_t addr) {
    asm volatile("ldmatrix.sync.aligned.m8n8.x4.trans.shared.b16 {%0,%1,%2,%3}, [%4];"
                 : "=r"(r0), "=r"(r1), "=r"(r2), "=r"(r3) : "r"(addr));
}

// ===========================================================================
// fp32 -> fp16 converts: ONE launch for x + all four weight matrices.
// ===========================================================================
#define XBLOCKS 2048
#define WBLOCKS_PER_SEG 256

__global__ void __launch_bounds__(256) f2h_all(const float* __restrict__ x,
                                               const float* __restrict__ wq,
                                               const float* __restrict__ wk,
                                               const float* __restrict__ wv,
                                               const float* __restrict__ wo,
                                               __half* __restrict__ xh,
                                               __half* __restrict__ wqkvh,
                                               __half* __restrict__ woh) {
    const int blk = blockIdx.x;
    if (blk < XBLOCKS) {
        const int nt = XBLOCKS * 256;
        const int i0 = blk * 256 + threadIdx.x;
#pragma unroll
        for (int p = 0; p < 4; p++) {
            const int i = i0 + p * nt;
            float4 v = ((const float4*)x)[i];
            ((uint2*)xh)[i] = make_uint2(f2h2(v.x, v.y), f2h2(v.z, v.w));
        }
    } else {
        const int wb  = blk - XBLOCKS;
        const int seg = wb / WBLOCKS_PER_SEG;
        const int ib  = wb % WBLOCKS_PER_SEG;
        const float* src = (seg == 0) ? wq : (seg == 1) ? wk : (seg == 2) ? wv : wo;
        __half* dst = (seg < 3) ? (wqkvh + (size_t)seg * D_DIM * D_DIM) : woh;
        const int nt = WBLOCKS_PER_SEG * 256;
        const int i0 = ib * 256 + threadIdx.x;
#pragma unroll
        for (int p = 0; p < 4; p++) {
            const int i = i0 + p * nt;
            float4 v = ((const float4*)src)[i];
            ((uint2*)dst)[i] = make_uint2(f2h2(v.x, v.y), f2h2(v.z, v.w));
        }
    }
}

// ===========================================================================
// fp16 NT GEMM (R14 config, unchanged): CTA 128x128, 128 threads
// (4 warps 2Mx2N, 64x64), KC=64, 3-stage cp.async, occ 2,
// fragment double-buffering.
// ===========================================================================
#define GKC        64
#define GSTR       72
#define GSTAGES    3
#define GTILE_H    (128 * GSTR)
#define GSTAGE_H   (2 * GTILE_H)
#define GEMM_SMEM  (GSTAGES * GSTAGE_H * 2)   // 110592 bytes

template <typename OutT>
__global__ void __launch_bounds__(128, 2) gemm_h(const __half* __restrict__ A,
                                                 const __half* __restrict__ B,
                                                 OutT* __restrict__ C,
                                                 int M, int N, int K) {
    extern __shared__ __half sh[];
    const uint32_t sbase = (uint32_t)__cvta_generic_to_shared(sh);

    const int tid  = threadIdx.x;
    const int lane = tid & 31;
    const int wid  = tid >> 5;
    const int g    = lane >> 2;
    const int t    = lane & 3;
    const int wm   = (wid & 1) * 64;
    const int wn   = (wid >> 1) * 64;
    const int bm   = blockIdx.y * 128;
    const int bn   = blockIdx.x * 128;

    const int arow = (lane & 7) + ((lane & 8) ? 8 : 0);
    const int acol = (lane & 16) ? 8 : 0;
    const int brow = (lane & 7) + ((lane & 16) ? 8 : 0);
    const int bcol = (lane & 8) ? 8 : 0;

    float acc[4][8][4];
#pragma unroll
    for (int i = 0; i < 4; i++)
#pragma unroll
        for (int j = 0; j < 8; j++)
#pragma unroll
            for (int q = 0; q < 4; q++) acc[i][j][q] = 0.0f;

    const int CHUNKS = K / GKC;

    auto issue = [&](int chunk, int st) {
        const __half* Agc = A + (size_t)bm * K + chunk * GKC;
        const __half* Bgc = B + (size_t)bn * K + chunk * GKC;
        const uint32_t sA = sbase + (uint32_t)(st * GSTAGE_H) * 2;
        const uint32_t sB = sA + (uint32_t)GTILE_H * 2;
#pragma unroll
        for (int i = 0; i < 8; i++) {
            const int cid = tid + i * 128;
            const int row = cid >> 3, c16 = cid & 7;
            const __half* ga = Agc + (size_t)row * K + c16 * 8;
            const __half* gb = Bgc + (size_t)row * K + c16 * 8;
            const uint32_t da = sA + (uint32_t)(row * GSTR + c16 * 8) * 2;
            const uint32_t db = sB + (uint32_t)(row * GSTR + c16 * 8) * 2;
            asm volatile("cp.async.cg.shared.global [%0], [%1], 16;" :: "r"(da), "l"(ga));
            asm volatile("cp.async.cg.shared.global [%0], [%1], 16;" :: "r"(db), "l"(gb));
        }
    };

#pragma unroll
    for (int s = 0; s < GSTAGES - 1; s++) {
        issue(s, s);
        asm volatile("cp.async.commit_group;");
    }

    uint32_t af[2][4][4], bf[2][8][2];

    for (int c = 0; c < CHUNKS; c++) {
        const int nc = c + GSTAGES - 1;
        if (nc < CHUNKS) issue(nc, nc % GSTAGES);
        asm volatile("cp.async.commit_group;");
        asm volatile("cp.async.wait_group 2;");
        __syncthreads();

        const int st = c % GSTAGES;
        const uint32_t aBase = sbase + (uint32_t)(st * GSTAGE_H) * 2;
        const uint32_t bBase = aBase + (uint32_t)GTILE_H * 2;

#pragma unroll
        for (int im = 0; im < 4; im++) {
            const uint32_t addr =
                aBase + (uint32_t)((wm + im * 16 + arow) * GSTR + acol) * 2;
            ldm_x4(af[0][im][0], af[0][im][1], af[0][im][2], af[0][im][3], addr);
        }
#pragma unroll
        for (int p = 0; p < 4; p++) {
            uint32_t r0, r1, r2, r3;
            const uint32_t addr =
                bBase + (uint32_t)((wn + p * 16 + brow) * GSTR + bcol) * 2;
            ldm_x4(r0, r1, r2, r3, addr);
            bf[0][2 * p][0] = r0; bf[0][2 * p][1] = r1;
            bf[0][2 * p + 1][0] = r2; bf[0][2 * p + 1][1] = r3;
        }

#pragma unroll
        for (int kb = 0; kb < 4; kb++) {
            const int cur = kb & 1;
            if (kb < 3) {
                const int nxt = (kb + 1) & 1;
#pragma unroll
                for (int im = 0; im < 4; im++) {
                    const uint32_t addr = aBase +
                        (uint32_t)((wm + im * 16 + arow) * GSTR + (kb + 1) * 16 + acol) * 2;
                    ldm_x4(af[nxt][im][0], af[nxt][im][1],
                           af[nxt][im][2], af[nxt][im][3], addr);
                }
#pragma unroll
                for (int p = 0; p < 4; p++) {
                    uint32_t r0, r1, r2, r3;
                    const uint32_t addr = bBase +
                        (uint32_t)((wn + p * 16 + brow) * GSTR + (kb + 1) * 16 + bcol) * 2;
                    ldm_x4(r0, r1, r2, r3, addr);
                    bf[nxt][2 * p][0] = r0; bf[nxt][2 * p][1] = r1;
                    bf[nxt][2 * p + 1][0] = r2; bf[nxt][2 * p + 1][1] = r3;
                }
            }
#pragma unroll
            for (int im = 0; im < 4; im++)
#pragma unroll
                for (int jn = 0; jn < 8; jn++)
                    mma_f16(acc[im][jn], af[cur][im], bf[cur][jn]);
        }
        __syncthreads();
    }

#pragma unroll
    for (int im = 0; im < 4; im++) {
#pragma unroll
        for (int jn = 0; jn < 8; jn++) {
            const int row = bm + wm + im * 16 + g;
            const int col = bn + wn + jn * 8 + 2 * t;
            if constexpr (sizeof(OutT) == 2) {
                *(uint32_t*)((__half*)C + (size_t)row * N + col) =
                    f2h2(acc[im][jn][0], acc[im][jn][1]);
                *(uint32_t*)((__half*)C + (size_t)(row + 8) * N + col) =
                    f2h2(acc[im][jn][2], acc[im][jn][3]);
            } else {
                *(float2*)((float*)C + (size_t)row * N + col) =
                    make_float2(acc[im][jn][0], acc[im][jn][1]);
                *(float2*)((float*)C + (size_t)(row + 8) * N + col) =
                    make_float2(acc[im][jn][2], acc[im][jn][3]);
            }
        }
    }
}

// ===========================================================================
// Causal flash attention: fp16 in/out, fp32 accum.
// R15: softmax exponentials via ex2.approx.f16x2 — halves MUFU pressure
// (the co-limiting pipe) and produces P fragments directly in fp16x2.
// ===========================================================================
#define QT   128
#define KT   64
#define AST  72
#define ATTN_SMEM ((9216 + 18432) * 2)   // 55296 bytes
#define C_SEXP 0.180336880f              // 0.125 * log2(e)

__global__ void __launch_bounds__(256, 2) attn_mma(const __half* __restrict__ QKV,
                                                   __half* __restrict__ O) {
    extern __shared__ __half ash[];
    const uint32_t sbase = (uint32_t)__cvta_generic_to_shared(ash);
    const uint32_t qsm = sbase;

    const int bh = blockIdx.y;
    const int b  = bh >> 4;
    const int h  = bh & 15;
    const int q0 = (int)(gridDim.x - 1 - blockIdx.x) * QT;

    const int tid  = threadIdx.x;
    const int lane = tid & 31;
    const int wid  = tid >> 5;
    const int g    = lane >> 2;
    const int t    = lane & 3;
    const int row0 = wid * 16;

    const int arow = (lane & 7) + ((lane & 8) ? 8 : 0);
    const int acol = (lane & 16) ? 8 : 0;
    const int brow = (lane & 7) + ((lane & 16) ? 8 : 0);
    const int bcol = (lane & 8) ? 8 : 0;

    const size_t qkv_base = ((size_t)b * S_LEN) * NQKV + (size_t)h * DHD;
    const __half* Qg = QKV + qkv_base;
    const __half* Kg = QKV + qkv_base + D_DIM;
    const __half* Vg = QKV + qkv_base + 2 * D_DIM;
    const size_t obase = ((size_t)b * S_LEN) * D_DIM + (size_t)h * DHD;

    const int ntiles = q0 / KT + 2;

    auto issueKV = [&](int tile) {
        const int st = tile & 1;
        const uint32_t kB = sbase + (uint32_t)(9216 + st * 9216) * 2;
        const uint32_t vB = kB + (uint32_t)4608 * 2;
        const __half* Kt = Kg + (size_t)(tile * KT) * NQKV;
        const __half* Vt = Vg + (size_t)(tile * KT) * NQKV;
#pragma unroll
        for (int i = 0; i < 2; i++) {
            const int cid = tid + i * 256;
            const int row = cid >> 3, c16 = cid & 7;
            const __half* gk = Kt + (size_t)row * NQKV + c16 * 8;
            const __half* gv = Vt + (size_t)row * NQKV + c16 * 8;
            const uint32_t dk = kB + (uint32_t)(row * AST + c16 * 8) * 2;
            const uint32_t dv = vB + (uint32_t)(row * AST + c16 * 8) * 2;
            asm volatile("cp.async.cg.shared.global [%0], [%1], 16;" :: "r"(dk), "l"(gk));
            asm volatile("cp.async.cg.shared.global [%0], [%1], 16;" :: "r"(dv), "l"(gv));
        }
        asm volatile("cp.async.commit_group;");
    };

    issueKV(0);

#pragma unroll
    for (int i = 0; i < 4; i++) {
        const int cid = tid + i * 256;
        const int row = cid >> 3, c16 = cid & 7;
        uint4 v = *(const uint4*)(Qg + (size_t)(q0 + row) * NQKV + c16 * 8);
        *(uint4*)(ash + row * AST + c16 * 8) = v;
    }
    __syncthreads();

    uint32_t qf[4][4];
#pragma unroll
    for (int kb = 0; kb < 4; kb++) {
        const uint32_t addr =
            qsm + (uint32_t)((row0 + arow) * AST + kb * 16 + acol) * 2;
        ldm_x4(qf[kb][0], qf[kb][1], qf[kb][2], qf[kb][3], addr);
    }

    float m0 = -1e30f, m1 = -1e30f, l0 = 0.0f, l1 = 0.0f;
    float o[8][4];
#pragma unroll
    for (int n = 0; n < 8; n++)
#pragma unroll
        for (int q = 0; q < 4; q++) o[n][q] = 0.0f;

    const int qg0 = q0 + row0 + g;
    const int qg1 = qg0 + 8;

    for (int tile = 0; tile < ntiles; tile++) {
        const int kv0 = tile * KT;

        __syncthreads();
        if (tile + 1 < ntiles) issueKV(tile + 1);
        else asm volatile("cp.async.commit_group;");
        asm volatile("cp.async.wait_group 1;");
        __syncthreads();

        const int st = tile & 1;
        const uint32_t kbase = sbase + (uint32_t)(9216 + st * 9216) * 2;
        const uint32_t vbase = kbase + (uint32_t)4608 * 2;

        if (kv0 <= q0 + row0 + 15) {
            float s[8][4];
#pragma unroll
            for (int n = 0; n < 8; n++)
#pragma unroll
                for (int q = 0; q < 4; q++) s[n][q] = 0.0f;

#pragma unroll
            for (int kb = 0; kb < 4; kb++) {
#pragma unroll
                for (int p = 0; p < 4; p++) {
                    uint32_t r0, r1, r2, r3;
                    const uint32_t addr =
                        kbase + (uint32_t)((p * 16 + brow) * AST + kb * 16 + bcol) * 2;
                    ldm_x4(r0, r1, r2, r3, addr);
                    uint32_t bf0[2] = {r0, r1};
                    uint32_t bf1[2] = {r2, r3};
                    mma_f16(s[2 * p],     qf[kb], bf0);
                    mma_f16(s[2 * p + 1], qf[kb], bf1);
                }
            }

            // ---- Causal mask (unscaled domain) ----
            if ((kv0 + KT - 1) > (q0 + row0)) {
#pragma unroll
                for (int n = 0; n < 8; n++) {
#pragma unroll
                    for (int e = 0; e < 2; e++) {
                        const int kg = kv0 + n * 8 + 2 * t + e;
                        if (kg > qg0) s[n][e]     = -1e30f;
                        if (kg > qg1) s[n][2 + e] = -1e30f;
                    }
                }
            }

            // ---- Row max (quad-local) ----
            float mt0 = -1e30f, mt1 = -1e30f;
#pragma unroll
            for (int n = 0; n < 8; n++) {
                mt0 = fmaxf(mt0, fmaxf(s[n][0], s[n][1]));
                mt1 = fmaxf(mt1, fmaxf(s[n][2], s[n][3]));
            }
            mt0 = fmaxf(mt0, __shfl_xor_sync(0xffffffffu, mt0, 1));
            mt0 = fmaxf(mt0, __shfl_xor_sync(0xffffffffu, mt0, 2));
            mt1 = fmaxf(mt1, __shfl_xor_sync(0xffffffffu, mt1, 1));
            mt1 = fmaxf(mt1, __shfl_xor_sync(0xffffffffu, mt1, 2));

            const float mn0 = fmaxf(m0, mt0);
            const float mn1 = fmaxf(m1, mt1);
            const float cr0 = exp2f((m0 - mn0) * C_SEXP);
            const float cr1 = exp2f((m1 - mn1) * C_SEXP);
            m0 = mn0; m1 = mn1;
            const float d0 = -mn0 * C_SEXP;
            const float d1 = -mn1 * C_SEXP;

            // ---- p = ex2.f16x2(fma(s,C,d) packed): P fragments direct ----
            uint32_t pl[8], ph[8];
            float lt0 = 0.0f, lt1 = 0.0f;
#pragma unroll
            for (int n = 0; n < 8; n++) {
                const float a0 = fmaf(s[n][0], C_SEXP, d0);
                const float a1 = fmaf(s[n][1], C_SEXP, d0);
                const float a2 = fmaf(s[n][2], C_SEXP, d1);
                const float a3 = fmaf(s[n][3], C_SEXP, d1);
                pl[n] = ex2_h2(f2h2(a0, a1));
                ph[n] = ex2_h2(f2h2(a2, a3));
                const float2 flo = __half22float2(*(const __half2*)&pl[n]);
                const float2 fhi = __half22float2(*(const __half2*)&ph[n]);
                lt0 += flo.x + flo.y;
                lt1 += fhi.x + fhi.y;
            }
            lt0 += __shfl_xor_sync(0xffffffffu, lt0, 1);
            lt0 += __shfl_xor_sync(0xffffffffu, lt0, 2);
            lt1 += __shfl_xor_sync(0xffffffffu, lt1, 1);
            lt1 += __shfl_xor_sync(0xffffffffu, lt1, 2);
            l0 = l0 * cr0 + lt0;
            l1 = l1 * cr1 + lt1;

#pragma unroll
            for (int n = 0; n < 8; n++) {
                o[n][0] *= cr0; o[n][1] *= cr0;
                o[n][2] *= cr1; o[n][3] *= cr1;
            }

            // ---- O += P V (P fragments are pl/ph directly) ----
#pragma unroll
            for (int kb = 0; kb < 4; kb++) {
                uint32_t ap[4];
                ap[0] = pl[2 * kb];
                ap[1] = ph[2 * kb];
                ap[2] = pl[2 * kb + 1];
                ap[3] = ph[2 * kb + 1];
#pragma unroll
                for (int p = 0; p < 4; p++) {
                    uint32_t r0, r1, r2, r3;
                    const uint32_t addr =
                        vbase + (uint32_t)((kb * 16 + arow) * AST + p * 16 + acol) * 2;
                    ldm_x4_t(r0, r1, r2, r3, addr);
                    uint32_t bf0[2] = {r0, r1};
                    uint32_t bf1[2] = {r2, r3};
                    mma_f16(o[2 * p],     ap, bf0);
                    mma_f16(o[2 * p + 1], ap, bf1);
                }
            }
        }
    }

    const float inv0 = 1.0f / l0;
    const float inv1 = 1.0f / l1;
#pragma unroll
    for (int n = 0; n < 8; n++) {
        const int col = n * 8 + 2 * t;
        *(uint32_t*)(O + obase + (size_t)qg0 * D_DIM + col) =
            f2h2(o[n][0] * inv0, o[n][1] * inv0);
        *(uint32_t*)(O + obase + (size_t)qg1 * D_DIM + col) =
            f2h2(o[n][2] * inv1, o[n][3] * inv1);
    }
}

// ===========================================================================
extern "C" void kernel_launch(void* const* d_in, const int* in_sizes, int n_in,
                              void* d_out, int out_size) {
    const float* x  = (const float*)d_in[0];
    const float* wq = (const float*)d_in[1];
    const float* wk = (const float*)d_in[2];
    const float* wv = (const float*)d_in[3];
    const float* wo = (const float*)d_in[4];
    float* out = (float*)d_out;

    __half *xh, *wqkvh, *woh, *QKVh, *aoh;
    cudaGetSymbolAddress((void**)&xh,    g_xh);
    cudaGetSymbolAddress((void**)&wqkvh, g_wqkvh);
    cudaGetSymbolAddress((void**)&woh,   g_woh);
    cudaGetSymbolAddress((void**)&QKVh,  g_QKVh);
    cudaGetSymbolAddress((void**)&aoh,   g_aoh);

    cudaFuncSetAttribute(gemm_h<__half>,
                         cudaFuncAttributeMaxDynamicSharedMemorySize, GEMM_SMEM);
    cudaFuncSetAttribute(gemm_h<float>,
                         cudaFuncAttributeMaxDynamicSharedMemorySize, GEMM_SMEM);
    cudaFuncSetAttribute(attn_mma,
                         cudaFuncAttributeMaxDynamicSharedMemorySize, ATTN_SMEM);

    f2h_all<<<XBLOCKS + 4 * WBLOCKS_PER_SEG, 256>>>(x, wq, wk, wv, wo,
                                                    xh, wqkvh, woh);

    gemm_h<__half><<<dim3(NQKV / 128, M_ROWS / 128), 128, GEMM_SMEM>>>(
        xh, wqkvh, QKVh, M_ROWS, NQKV, D_DIM);

    attn_mma<<<dim3(S_LEN / QT, NB * NH), 256, ATTN_SMEM>>>(QKVh, aoh);

    gemm_h<float><<<dim3(D_DIM / 128, M_ROWS / 128), 128, GEMM_SMEM>>>(
        aoh, woh, out, M_ROWS, D_DIM, D_DIM);
}

// round 16
// speedup vs baseline: 1.0341x; 1.0052x over previous
#include <cuda_runtime.h>
#include <cuda_fp16.h>
#include <cstdint>

// Problem constants
#define S_LEN 2048
#define D_DIM 1024
#define NB    4
#define NH    16
#define DHD   64
#define M_ROWS (NB * S_LEN)   // 8192
#define NQKV  (3 * D_DIM)     // 3072

// Scratch (device globals: allocation-free per harness rules)
__device__ __half g_xh   [M_ROWS * D_DIM];
__device__ __half g_wqkvh[NQKV * D_DIM];
__device__ __half g_woh  [D_DIM * D_DIM];
__device__ __half g_QKVh [M_ROWS * NQKV];
__device__ __half g_aoh  [M_ROWS * D_DIM];

// ===========================================================================
// Helpers
// ===========================================================================
__device__ __forceinline__ uint32_t f2h2(float lo, float hi) {
    uint32_t u;
    asm("cvt.rn.f16x2.f32 %0, %1, %2;" : "=r"(u) : "f"(hi), "f"(lo));
    return u;
}

__device__ __forceinline__ uint32_t ex2_h2(uint32_t arg) {
    uint32_t r;
    asm("ex2.approx.f16x2 %0, %1;" : "=r"(r) : "r"(arg));
    return r;
}

__device__ __forceinline__ void mma_f16(float c[4], const uint32_t a[4],
                                        const uint32_t b[2]) {
    asm volatile(
        "mma.sync.aligned.m16n8k16.row.col.f32.f16.f16.f32 "
        "{%0,%1,%2,%3}, {%4,%5,%6,%7}, {%8,%9}, {%0,%1,%2,%3};"
        : "+f"(c[0]), "+f"(c[1]), "+f"(c[2]), "+f"(c[3])
        : "r"(a[0]), "r"(a[1]), "r"(a[2]), "r"(a[3]), "r"(b[0]), "r"(b[1]));
}

__device__ __forceinline__ void ldm_x4(uint32_t& r0, uint32_t& r1,
                                       uint32_t& r2, uint32_t& r3,
                                       uint32_t addr) {
    asm volatile("ldmatrix.sync.aligned.m8n8.x4.shared.b16 {%0,%1,%2,%3}, [%4];"
                 : "=r"(r0), "=r"(r1), "=r"(r2), "=r"(r3) : "r"(addr));
}
__device__ __forceinline__ void ldm_x4_t(uint32_t& r0, uint32_t& r1,
                                         uint32_t& r2, uint32_t& r3,
                                         uint32_t addr) {
    asm volatile("ldmatrix.sync.aligned.m8n8.x4.trans.shared.b16 {%0,%1,%2,%3}, [%4];"
                 : "=r"(r0), "=r"(r1), "=r"(r2), "=r"(r3) : "r"(addr));
}

// ===========================================================================
// fp32 -> fp16 converts: ONE launch for x + all four weight matrices.
// ===========================================================================
#define XBLOCKS 2048
#define WBLOCKS_PER_SEG 256

__global__ void __launch_bounds__(256) f2h_all(const float* __restrict__ x,
                                               const float* __restrict__ wq,
                                               const float* __restrict__ wk,
                                               const float* __restrict__ wv,
                                               const float* __restrict__ wo,
                                               __half* __restrict__ xh,
                                               __half* __restrict__ wqkvh,
                                               __half* __restrict__ woh) {
    const int blk = blockIdx.x;
    if (blk < XBLOCKS) {
        const int nt = XBLOCKS * 256;
        const int i0 = blk * 256 + threadIdx.x;
#pragma unroll
        for (int p = 0; p < 4; p++) {
            const int i = i0 + p * nt;
            float4 v = ((const float4*)x)[i];
            ((uint2*)xh)[i] = make_uint2(f2h2(v.x, v.y), f2h2(v.z, v.w));
        }
    } else {
        const int wb  = blk - XBLOCKS;
        const int seg = wb / WBLOCKS_PER_SEG;
        const int ib  = wb % WBLOCKS_PER_SEG;
        const float* src = (seg == 0) ? wq : (seg == 1) ? wk : (seg == 2) ? wv : wo;
        __half* dst = (seg < 3) ? (wqkvh + (size_t)seg * D_DIM * D_DIM) : woh;
        const int nt = WBLOCKS_PER_SEG * 256;
        const int i0 = ib * 256 + threadIdx.x;
#pragma unroll
        for (int p = 0; p < 4; p++) {
            const int i = i0 + p * nt;
            float4 v = ((const float4*)src)[i];
            ((uint2*)dst)[i] = make_uint2(f2h2(v.x, v.y), f2h2(v.z, v.w));
        }
    }
}

// ===========================================================================
// fp16 NT GEMM (R14 config, unchanged): CTA 128x128, 128 threads
// (4 warps 2Mx2N, 64x64), KC=64, 3-stage cp.async, occ 2,
// fragment double-buffering.
// ===========================================================================
#define GKC        64
#define GSTR       72
#define GSTAGES    3
#define GTILE_H    (128 * GSTR)
#define GSTAGE_H   (2 * GTILE_H)
#define GEMM_SMEM  (GSTAGES * GSTAGE_H * 2)   // 110592 bytes

template <typename OutT>
__global__ void __launch_bounds__(128, 2) gemm_h(const __half* __restrict__ A,
                                                 const __half* __restrict__ B,
                                                 OutT* __restrict__ C,
                                                 int M, int N, int K) {
    extern __shared__ __half sh[];
    const uint32_t sbase = (uint32_t)__cvta_generic_to_shared(sh);

    const int tid  = threadIdx.x;
    const int lane = tid & 31;
    const int wid  = tid >> 5;
    const int g    = lane >> 2;
    const int t    = lane & 3;
    const int wm   = (wid & 1) * 64;
    const int wn   = (wid >> 1) * 64;
    const int bm   = blockIdx.y * 128;
    const int bn   = blockIdx.x * 128;

    const int arow = (lane & 7) + ((lane & 8) ? 8 : 0);
    const int acol = (lane & 16) ? 8 : 0;
    const int brow = (lane & 7) + ((lane & 16) ? 8 : 0);
    const int bcol = (lane & 8) ? 8 : 0;

    float acc[4][8][4];
#pragma unroll
    for (int i = 0; i < 4; i++)
#pragma unroll
        for (int j = 0; j < 8; j++)
#pragma unroll
            for (int q = 0; q < 4; q++) acc[i][j][q] = 0.0f;

    const int CHUNKS = K / GKC;

    auto issue = [&](int chunk, int st) {
        const __half* Agc = A + (size_t)bm * K + chunk * GKC;
        const __half* Bgc = B + (size_t)bn * K + chunk * GKC;
        const uint32_t sA = sbase + (uint32_t)(st * GSTAGE_H) * 2;
        const uint32_t sB = sA + (uint32_t)GTILE_H * 2;
#pragma unroll
        for (int i = 0; i < 8; i++) {
            const int cid = tid + i * 128;
            const int row = cid >> 3, c16 = cid & 7;
            const __half* ga = Agc + (size_t)row * K + c16 * 8;
            const __half* gb = Bgc + (size_t)row * K + c16 * 8;
            const uint32_t da = sA + (uint32_t)(row * GSTR + c16 * 8) * 2;
            const uint32_t db = sB + (uint32_t)(row * GSTR + c16 * 8) * 2;
            asm volatile("cp.async.cg.shared.global [%0], [%1], 16;" :: "r"(da), "l"(ga));
            asm volatile("cp.async.cg.shared.global [%0], [%1], 16;" :: "r"(db), "l"(gb));
        }
    };

#pragma unroll
    for (int s = 0; s < GSTAGES - 1; s++) {
        issue(s, s);
        asm volatile("cp.async.commit_group;");
    }

    uint32_t af[2][4][4], bf[2][8][2];

    for (int c = 0; c < CHUNKS; c++) {
        const int nc = c + GSTAGES - 1;
        if (nc < CHUNKS) issue(nc, nc % GSTAGES);
        asm volatile("cp.async.commit_group;");
        asm volatile("cp.async.wait_group 2;");
        __syncthreads();

        const int st = c % GSTAGES;
        const uint32_t aBase = sbase + (uint32_t)(st * GSTAGE_H) * 2;
        const uint32_t bBase = aBase + (uint32_t)GTILE_H * 2;

#pragma unroll
        for (int im = 0; im < 4; im++) {
            const uint32_t addr =
                aBase + (uint32_t)((wm + im * 16 + arow) * GSTR + acol) * 2;
            ldm_x4(af[0][im][0], af[0][im][1], af[0][im][2], af[0][im][3], addr);
        }
#pragma unroll
        for (int p = 0; p < 4; p++) {
            uint32_t r0, r1, r2, r3;
            const uint32_t addr =
                bBase + (uint32_t)((wn + p * 16 + brow) * GSTR + bcol) * 2;
            ldm_x4(r0, r1, r2, r3, addr);
            bf[0][2 * p][0] = r0; bf[0][2 * p][1] = r1;
            bf[0][2 * p + 1][0] = r2; bf[0][2 * p + 1][1] = r3;
        }

#pragma unroll
        for (int kb = 0; kb < 4; kb++) {
            const int cur = kb & 1;
            if (kb < 3) {
                const int nxt = (kb + 1) & 1;
#pragma unroll
                for (int im = 0; im < 4; im++) {
                    const uint32_t addr = aBase +
                        (uint32_t)((wm + im * 16 + arow) * GSTR + (kb + 1) * 16 + acol) * 2;
                    ldm_x4(af[nxt][im][0], af[nxt][im][1],
                           af[nxt][im][2], af[nxt][im][3], addr);
                }
#pragma unroll
                for (int p = 0; p < 4; p++) {
                    uint32_t r0, r1, r2, r3;
                    const uint32_t addr = bBase +
                        (uint32_t)((wn + p * 16 + brow) * GSTR + (kb + 1) * 16 + bcol) * 2;
                    ldm_x4(r0, r1, r2, r3, addr);
                    bf[nxt][2 * p][0] = r0; bf[nxt][2 * p][1] = r1;
                    bf[nxt][2 * p + 1][0] = r2; bf[nxt][2 * p + 1][1] = r3;
                }
            }
#pragma unroll
            for (int im = 0; im < 4; im++)
#pragma unroll
                for (int jn = 0; jn < 8; jn++)
                    mma_f16(acc[im][jn], af[cur][im], bf[cur][jn]);
        }
        __syncthreads();
    }

#pragma unroll
    for (int im = 0; im < 4; im++) {
#pragma unroll
        for (int jn = 0; jn < 8; jn++) {
            const int row = bm + wm + im * 16 + g;
            const int col = bn + wn + jn * 8 + 2 * t;
            if constexpr (sizeof(OutT) == 2) {
                *(uint32_t*)((__half*)C + (size_t)row * N + col) =
                    f2h2(acc[im][jn][0], acc[im][jn][1]);
                *(uint32_t*)((__half*)C + (size_t)(row + 8) * N + col) =
                    f2h2(acc[im][jn][2], acc[im][jn][3]);
            } else {
                *(float2*)((float*)C + (size_t)row * N + col) =
                    make_float2(acc[im][jn][0], acc[im][jn][1]);
                *(float2*)((float*)C + (size_t)(row + 8) * N + col) =
                    make_float2(acc[im][jn][2], acc[im][jn][3]);
            }
        }
    }
}

// ===========================================================================
// Causal flash attention: fp16 in/out, fp32 accum.
// R16: K/V loaded in 128-row tiles (halves barrier pairs + pipeline turns
// per kv element); two 64-col compute sub-steps reuse the same registers.
// Softmax via ex2.approx.f16x2 (R15).
// ===========================================================================
#define QT   128
#define KTL  128                         // kv load-tile (2 compute sub-steps)
#define AST  72
// halves: Q 128*72 = 9216; 2 stages x (K 128*72 + V 128*72 = 18432) = 36864
#define ATTN_SMEM ((9216 + 36864) * 2)   // 92160 bytes
#define C_SEXP 0.180336880f              // 0.125 * log2(e)

__global__ void __launch_bounds__(256, 2) attn_mma(const __half* __restrict__ QKV,
                                                   __half* __restrict__ O) {
    extern __shared__ __half ash[];
    const uint32_t sbase = (uint32_t)__cvta_generic_to_shared(ash);
    const uint32_t qsm = sbase;

    const int bh = blockIdx.y;
    const int b  = bh >> 4;
    const int h  = bh & 15;
    const int q0 = (int)(gridDim.x - 1 - blockIdx.x) * QT;

    const int tid  = threadIdx.x;
    const int lane = tid & 31;
    const int wid  = tid >> 5;
    const int g    = lane >> 2;
    const int t    = lane & 3;
    const int row0 = wid * 16;

    const int arow = (lane & 7) + ((lane & 8) ? 8 : 0);
    const int acol = (lane & 16) ? 8 : 0;
    const int brow = (lane & 7) + ((lane & 16) ? 8 : 0);
    const int bcol = (lane & 8) ? 8 : 0;

    const size_t qkv_base = ((size_t)b * S_LEN) * NQKV + (size_t)h * DHD;
    const __half* Qg = QKV + qkv_base;
    const __half* Kg = QKV + qkv_base + D_DIM;
    const __half* Vg = QKV + qkv_base + 2 * D_DIM;
    const size_t obase = ((size_t)b * S_LEN) * D_DIM + (size_t)h * DHD;

    const int ntiles = q0 / KTL + 1;   // 128-row kv tiles cover [0, q0+128)

    auto issueKV = [&](int tile) {
        const int st = tile & 1;
        const uint32_t kB = sbase + (uint32_t)(9216 + st * 18432) * 2;
        const uint32_t vB = kB + (uint32_t)(128 * AST) * 2;
        const __half* Kt = Kg + (size_t)(tile * KTL) * NQKV;
        const __half* Vt = Vg + (size_t)(tile * KTL) * NQKV;
#pragma unroll
        for (int i = 0; i < 4; i++) {
            const int cid = tid + i * 256;
            const int row = cid >> 3, c16 = cid & 7;
            const __half* gk = Kt + (size_t)row * NQKV + c16 * 8;
            const __half* gv = Vt + (size_t)row * NQKV + c16 * 8;
            const uint32_t dk = kB + (uint32_t)(row * AST + c16 * 8) * 2;
            const uint32_t dv = vB + (uint32_t)(row * AST + c16 * 8) * 2;
            asm volatile("cp.async.cg.shared.global [%0], [%1], 16;" :: "r"(dk), "l"(gk));
            asm volatile("cp.async.cg.shared.global [%0], [%1], 16;" :: "r"(dv), "l"(gv));
        }
        asm volatile("cp.async.commit_group;");
    };

    issueKV(0);

#pragma unroll
    for (int i = 0; i < 4; i++) {
        const int cid = tid + i * 256;
        const int row = cid >> 3, c16 = cid & 7;
        uint4 v = *(const uint4*)(Qg + (size_t)(q0 + row) * NQKV + c16 * 8);
        *(uint4*)(ash + row * AST + c16 * 8) = v;
    }
    __syncthreads();

    uint32_t qf[4][4];
#pragma unroll
    for (int kb = 0; kb < 4; kb++) {
        const uint32_t addr =
            qsm + (uint32_t)((row0 + arow) * AST + kb * 16 + acol) * 2;
        ldm_x4(qf[kb][0], qf[kb][1], qf[kb][2], qf[kb][3], addr);
    }

    float m0 = -1e30f, m1 = -1e30f, l0 = 0.0f, l1 = 0.0f;
    float o[8][4];
#pragma unroll
    for (int n = 0; n < 8; n++)
#pragma unroll
        for (int q = 0; q < 4; q++) o[n][q] = 0.0f;

    const int qg0 = q0 + row0 + g;
    const int qg1 = qg0 + 8;

    for (int tile = 0; tile < ntiles; tile++) {
        __syncthreads();
        if (tile + 1 < ntiles) issueKV(tile + 1);
        else asm volatile("cp.async.commit_group;");
        asm volatile("cp.async.wait_group 1;");
        __syncthreads();

        const int st = tile & 1;
        const uint32_t kTile = sbase + (uint32_t)(9216 + st * 18432) * 2;
        const uint32_t vTile = kTile + (uint32_t)(128 * AST) * 2;

#pragma unroll
        for (int sub = 0; sub < 2; sub++) {
            const int kv0 = tile * KTL + sub * 64;
            if (kv0 > q0 + row0 + 15) continue;   // warp fully masked
            const uint32_t kbase = kTile + (uint32_t)(sub * 64 * AST) * 2;
            const uint32_t vbase = vTile + (uint32_t)(sub * 64 * AST) * 2;

            float s[8][4];
#pragma unroll
            for (int n = 0; n < 8; n++)
#pragma unroll
                for (int q = 0; q < 4; q++) s[n][q] = 0.0f;

#pragma unroll
            for (int kb = 0; kb < 4; kb++) {
#pragma unroll
                for (int p = 0; p < 4; p++) {
                    uint32_t r0, r1, r2, r3;
                    const uint32_t addr =
                        kbase + (uint32_t)((p * 16 + brow) * AST + kb * 16 + bcol) * 2;
                    ldm_x4(r0, r1, r2, r3, addr);
                    uint32_t bf0[2] = {r0, r1};
                    uint32_t bf1[2] = {r2, r3};
                    mma_f16(s[2 * p],     qf[kb], bf0);
                    mma_f16(s[2 * p + 1], qf[kb], bf1);
                }
            }

            // ---- Causal mask (unscaled domain) ----
            if ((kv0 + 63) > (q0 + row0)) {
#pragma unroll
                for (int n = 0; n < 8; n++) {
#pragma unroll
                    for (int e = 0; e < 2; e++) {
                        const int kg = kv0 + n * 8 + 2 * t + e;
                        if (kg > qg0) s[n][e]     = -1e30f;
                        if (kg > qg1) s[n][2 + e] = -1e30f;
                    }
                }
            }

            // ---- Row max (quad-local) ----
            float mt0 = -1e30f, mt1 = -1e30f;
#pragma unroll
            for (int n = 0; n < 8; n++) {
                mt0 = fmaxf(mt0, fmaxf(s[n][0], s[n][1]));
                mt1 = fmaxf(mt1, fmaxf(s[n][2], s[n][3]));
            }
            mt0 = fmaxf(mt0, __shfl_xor_sync(0xffffffffu, mt0, 1));
            mt0 = fmaxf(mt0, __shfl_xor_sync(0xffffffffu, mt0, 2));
            mt1 = fmaxf(mt1, __shfl_xor_sync(0xffffffffu, mt1, 1));
            mt1 = fmaxf(mt1, __shfl_xor_sync(0xffffffffu, mt1, 2));

            const float mn0 = fmaxf(m0, mt0);
            const float mn1 = fmaxf(m1, mt1);
            const float cr0 = exp2f((m0 - mn0) * C_SEXP);
            const float cr1 = exp2f((m1 - mn1) * C_SEXP);
            m0 = mn0; m1 = mn1;
            const float d0 = -mn0 * C_SEXP;
            const float d1 = -mn1 * C_SEXP;

            // ---- p = ex2.f16x2(fma(s,C,d) packed): P fragments direct ----
            uint32_t pl[8], ph[8];
            float lt0 = 0.0f, lt1 = 0.0f;
#pragma unroll
            for (int n = 0; n < 8; n++) {
                const float a0 = fmaf(s[n][0], C_SEXP, d0);
                const float a1 = fmaf(s[n][1], C_SEXP, d0);
                const float a2 = fmaf(s[n][2], C_SEXP, d1);
                const float a3 = fmaf(s[n][3], C_SEXP, d1);
                pl[n] = ex2_h2(f2h2(a0, a1));
                ph[n] = ex2_h2(f2h2(a2, a3));
                const float2 flo = __half22float2(*(const __half2*)&pl[n]);
                const float2 fhi = __half22float2(*(const __half2*)&ph[n]);
                lt0 += flo.x + flo.y;
                lt1 += fhi.x + fhi.y;
            }
            lt0 += __shfl_xor_sync(0xffffffffu, lt0, 1);
            lt0 += __shfl_xor_sync(0xffffffffu, lt0, 2);
            lt1 += __shfl_xor_sync(0xffffffffu, lt1, 1);
            lt1 += __shfl_xor_sync(0xffffffffu, lt1, 2);
            l0 = l0 * cr0 + lt0;
            l1 = l1 * cr1 + lt1;

#pragma unroll
            for (int n = 0; n < 8; n++) {
                o[n][0] *= cr0; o[n][1] *= cr0;
                o[n][2] *= cr1; o[n][3] *= cr1;
            }

            // ---- O += P V ----
#pragma unroll
            for (int kb = 0; kb < 4; kb++) {
                uint32_t ap[4];
                ap[0] = pl[2 * kb];
                ap[1] = ph[2 * kb];
                ap[2] = pl[2 * kb + 1];
                ap[3] = ph[2 * kb + 1];
#pragma unroll
                for (int p = 0; p < 4; p++) {
                    uint32_t r0, r1, r2, r3;
                    const uint32_t addr =
                        vbase + (uint32_t)((kb * 16 + arow) * AST + p * 16 + acol) * 2;
                    ldm_x4_t(r0, r1, r2, r3, addr);
                    uint32_t bf0[2] = {r0, r1};
                    uint32_t bf1[2] = {r2, r3};
                    mma_f16(o[2 * p],     ap, bf0);
                    mma_f16(o[2 * p + 1], ap, bf1);
                }
            }
        }
    }

    const float inv0 = 1.0f / l0;
    const float inv1 = 1.0f / l1;
#pragma unroll
    for (int n = 0; n < 8; n++) {
        const int col = n * 8 + 2 * t;
        *(uint32_t*)(O + obase + (size_t)qg0 * D_DIM + col) =
            f2h2(o[n][0] * inv0, o[n][1] * inv0);
        *(uint32_t*)(O + obase + (size_t)qg1 * D_DIM + col) =
            f2h2(o[n][2] * inv1, o[n][3] * inv1);
    }
}

// ===========================================================================
extern "C" void kernel_launch(void* const* d_in, const int* in_sizes, int n_in,
                              void* d_out, int out_size) {
    const float* x  = (const float*)d_in[0];
    const float* wq = (const float*)d_in[1];
    const float* wk = (const float*)d_in[2];
    const float* wv = (const float*)d_in[3];
    const float* wo = (const float*)d_in[4];
    float* out = (float*)d_out;

    __half *xh, *wqkvh, *woh, *QKVh, *aoh;
    cudaGetSymbolAddress((void**)&xh,    g_xh);
    cudaGetSymbolAddress((void**)&wqkvh, g_wqkvh);
    cudaGetSymbolAddress((void**)&woh,   g_woh);
    cudaGetSymbolAddress((void**)&QKVh,  g_QKVh);
    cudaGetSymbolAddress((void**)&aoh,   g_aoh);

    cudaFuncSetAttribute(gemm_h<__half>,
                         cudaFuncAttributeMaxDynamicSharedMemorySize, GEMM_SMEM);
    cudaFuncSetAttribute(gemm_h<float>,
                         cudaFuncAttributeMaxDynamicSharedMemorySize, GEMM_SMEM);
    cudaFuncSetAttribute(attn_mma,
                         cudaFuncAttributeMaxDynamicSharedMemorySize, ATTN_SMEM);

    f2h_all<<<XBLOCKS + 4 * WBLOCKS_PER_SEG, 256>>>(x, wq, wk, wv, wo,
                                                    xh, wqkvh, woh);

    gemm_h<__half><<<dim3(NQKV / 128, M_ROWS / 128), 128, GEMM_SMEM>>>(
        xh, wqkvh, QKVh, M_ROWS, NQKV, D_DIM);

    attn_mma<<<dim3(S_LEN / QT, NB * NH), 256, ATTN_SMEM>>>(QKVh, aoh);

    gemm_h<float><<<dim3(D_DIM / 128, M_ROWS / 128), 128, GEMM_SMEM>>>(
        aoh, woh, out, M_ROWS, D_DIM, D_DIM);
}